// round 3
// baseline (speedup 1.0000x reference)
#include <cuda_runtime.h>
#include <cstdint>

// ============================================================================
// out[M,N] = sign(x)[M,K] @ sign(w)[K,N],  M=8192, K=4096, N=4096
// Base-sm_103 path (NO tcgen05 — 'a'-features rejected by harness toolchain):
//   binarize to int8 {-1,0,+1}  ->  mma.sync.m16n8k32.s8.s8.s32  ->  f32 out
// Exact: s32 accumulation of +-1 terms, s32->f32 conversion exact (<2^24).
// ============================================================================

#define M_DIM 8192
#define N_DIM 4096
#define K_DIM 4096

#define BM 128
#define BN 256
#define BK 64
#define STAGES 5
#define KITERS (K_DIM / BK)          // 64
#define M_TILES (M_DIM / BM)         // 64
#define N_TILES (N_DIM / BN)         // 16
#define THREADS 512                   // 16 warps, 4(m) x 4(n), warp tile 32x64

#define PITCH 80                      // 64B data + 16B pad: conflict-free ldmatrix
#define ASTAGE (BM * PITCH)           // 10240
#define BSTAGE (BN * PITCH)           // 20480
#define STAGE_BYTES (ASTAGE + BSTAGE) // 30720
#define SMEM_TOTAL (STAGES * STAGE_BYTES) // 153600

// ---------------------------------------------------------------------------
// Scratch (allocation-free)
// ---------------------------------------------------------------------------
__device__ __align__(128) int8_t g_xa[(size_t)M_DIM * K_DIM]; // A [M,K] int8
__device__ __align__(128) int8_t g_wt[(size_t)N_DIM * K_DIM]; // B [N,K] int8 (w^T)

// ---------------------------------------------------------------------------
// Binarization
// ---------------------------------------------------------------------------
__device__ __forceinline__ int sgn8(float v) {
    return (v > 0.0f) - (v < 0.0f);
}
__device__ __forceinline__ uint32_t pack4(float a, float b, float c, float d) {
    return (uint32_t)(uint8_t)(int8_t)sgn8(a) |
           ((uint32_t)(uint8_t)(int8_t)sgn8(b) << 8) |
           ((uint32_t)(uint8_t)(int8_t)sgn8(c) << 16) |
           ((uint32_t)(uint8_t)(int8_t)sgn8(d) << 24);
}

// x [M,K] f32 -> g_xa [M,K] int8 (16 elems/thread)
__global__ void binarize_x_kernel(const float4* __restrict__ x, int n16) {
    int i = blockIdx.x * blockDim.x + threadIdx.x;
    if (i < n16) {
        float4 a = x[4 * i], b = x[4 * i + 1], c = x[4 * i + 2], d = x[4 * i + 3];
        uint4 r;
        r.x = pack4(a.x, a.y, a.z, a.w);
        r.y = pack4(b.x, b.y, b.z, b.w);
        r.z = pack4(c.x, c.y, c.z, c.w);
        r.w = pack4(d.x, d.y, d.z, d.w);
        reinterpret_cast<uint4*>(g_xa)[i] = r;
    }
}

// w [K,N] f32 -> g_wt [N,K] int8 (binarize + transpose)
__global__ void binarize_wT_kernel(const float* __restrict__ w) {
    __shared__ int8_t tile[32][33];
    int n0 = blockIdx.x * 32, k0 = blockIdx.y * 32;
    int tx = threadIdx.x, ty = threadIdx.y;
#pragma unroll
    for (int j = 0; j < 4; j++) {
        int k = k0 + ty + 8 * j;
        tile[ty + 8 * j][tx] = (int8_t)sgn8(w[(size_t)k * N_DIM + n0 + tx]);
    }
    __syncthreads();
#pragma unroll
    for (int j = 0; j < 4; j++) {
        int n = n0 + ty + 8 * j;
        g_wt[(size_t)n * K_DIM + k0 + tx] = tile[tx][ty + 8 * j];
    }
}

// ---------------------------------------------------------------------------
// PTX helpers (base sm_103 only: cp.async, ldmatrix, mma.sync — no 'a' feats)
// ---------------------------------------------------------------------------
__device__ __forceinline__ void cp16(uint32_t s, const void* g) {
    asm volatile("cp.async.cg.shared.global [%0], [%1], 16;" :: "r"(s), "l"(g));
}
__device__ __forceinline__ void cp_commit() {
    asm volatile("cp.async.commit_group;" ::: "memory");
}
__device__ __forceinline__ void cp_wait3() {
    asm volatile("cp.async.wait_group %0;" :: "n"(STAGES - 2) : "memory");
}
__device__ __forceinline__ void ldsm_x4(uint32_t* r, uint32_t addr) {
    asm volatile("ldmatrix.sync.aligned.m8n8.x4.shared.b16 {%0,%1,%2,%3}, [%4];"
                 : "=r"(r[0]), "=r"(r[1]), "=r"(r[2]), "=r"(r[3]) : "r"(addr));
}
__device__ __forceinline__ void imma(int* c, const uint32_t* a, uint32_t b0, uint32_t b1) {
    asm volatile(
        "mma.sync.aligned.m16n8k32.row.col.s32.s8.s8.s32 "
        "{%0,%1,%2,%3}, {%4,%5,%6,%7}, {%8,%9}, {%0,%1,%2,%3};"
        : "+r"(c[0]), "+r"(c[1]), "+r"(c[2]), "+r"(c[3])
        : "r"(a[0]), "r"(a[1]), "r"(a[2]), "r"(a[3]), "r"(b0), "r"(b1));
}

// ---------------------------------------------------------------------------
// GEMM: 128x256x64 CTA tile, 5-stage cp.async pipeline, 16 warps (32x64 each)
// ---------------------------------------------------------------------------
__global__ __launch_bounds__(THREADS, 1)
void gemm_kernel(float* __restrict__ out) {
    extern __shared__ char smem[];
    const uint32_t sbase = (uint32_t)__cvta_generic_to_shared(smem);
    const int tid = threadIdx.x;
    const int wid = tid >> 5;
    const int lane = tid & 31;

    const int mT = blockIdx.x & (M_TILES - 1);   // fast index: waves share B tiles
    const int nT = blockIdx.x >> 6;              // / M_TILES
    const int wm = wid & 3;                      // warp m index (0..3)
    const int wn = wid >> 2;                     // warp n index (0..3)

    // --- cp.async per-thread source/dest offsets ---
    // A tile: 128 rows x 64B = 512 x 16B chunks; chunk = tid
    const int a_row = tid >> 2, a_c16 = (tid & 3) * 16;
    const int8_t* gA = g_xa + (size_t)(mT * BM + a_row) * K_DIM + a_c16;
    const uint32_t sA = sbase + a_row * PITCH + a_c16;
    // B tile: 256 rows x 64B = 1024 chunks; chunks tid, tid+512
    const int b_row0 = tid >> 2, b_row1 = (tid + 512) >> 2;
    const int b_c16 = (tid & 3) * 16;
    const int8_t* gB0 = g_wt + (size_t)(nT * BN + b_row0) * K_DIM + b_c16;
    const int8_t* gB1 = g_wt + (size_t)(nT * BN + b_row1) * K_DIM + b_c16;
    const uint32_t sB0 = sbase + ASTAGE + b_row0 * PITCH + b_c16;
    const uint32_t sB1 = sbase + ASTAGE + b_row1 * PITCH + b_c16;

    // --- ldmatrix per-lane offsets (within a stage) ---
    const int l8 = lane & 7, quad = lane >> 3;
    // A, mt in {0,1}: matrices {rows, rows+8, rows|col+16, rows+8|col+16}
    uint32_t offA[2];
#pragma unroll
    for (int mt = 0; mt < 2; mt++)
        offA[mt] = (uint32_t)((wm * 32 + mt * 16 + (quad & 1) * 8 + l8) * PITCH +
                              (quad >> 1) * 16);
    // B, nt-pair p in {0..3}: matrices {nt0.b0, nt0.b1, nt1.b0, nt1.b1}
    uint32_t offB[4];
#pragma unroll
    for (int p = 0; p < 4; p++)
        offB[p] = (uint32_t)(ASTAGE + (wn * 64 + p * 16 + (quad >> 1) * 8 + l8) * PITCH +
                             (quad & 1) * 16);

    int c[2][8][4];
#pragma unroll
    for (int mt = 0; mt < 2; mt++)
#pragma unroll
        for (int nt = 0; nt < 8; nt++)
#pragma unroll
            for (int i = 0; i < 4; i++) c[mt][nt][i] = 0;

    // --- prologue: fill STAGES-1 stages ---
#pragma unroll
    for (int s = 0; s < STAGES - 1; s++) {
        const uint32_t so = s * STAGE_BYTES;
        const int ko = s * BK;
        cp16(sA + so, gA + ko);
        cp16(sB0 + so, gB0 + ko);
        cp16(sB1 + so, gB1 + ko);
        cp_commit();
    }

    // --- mainloop ---
    int slot = 0;
    for (int kt = 0; kt < KITERS; kt++) {
        cp_wait3();
        __syncthreads();

        // issue loads for stage kt+STAGES-1 into the slot just freed
        {
            const int kl = kt + STAGES - 1;
            if (kl < KITERS) {
                const int ws = (slot + STAGES - 1) % STAGES;
                const uint32_t so = ws * STAGE_BYTES;
                const int ko = kl * BK;
                cp16(sA + so, gA + ko);
                cp16(sB0 + so, gB0 + ko);
                cp16(sB1 + so, gB1 + ko);
            }
            cp_commit();
        }

        const uint32_t so = sbase ? slot * STAGE_BYTES : 0;  // keep in reg
        const uint32_t st = sbase + so;
#pragma unroll
        for (int ks = 0; ks < 2; ks++) {
            uint32_t a[2][4], b[4][4];
#pragma unroll
            for (int mt = 0; mt < 2; mt++) ldsm_x4(a[mt], st + offA[mt] + ks * 32);
#pragma unroll
            for (int p = 0; p < 4; p++) ldsm_x4(b[p], st + offB[p] + ks * 32);
#pragma unroll
            for (int mt = 0; mt < 2; mt++)
#pragma unroll
                for (int p = 0; p < 4; p++) {
                    imma(c[mt][2 * p + 0], a[mt], b[p][0], b[p][1]);
                    imma(c[mt][2 * p + 1], a[mt], b[p][2], b[p][3]);
                }
        }
        if (++slot == STAGES) slot = 0;
    }

    // --- epilogue: s32 -> f32 (exact), coalescible 8B stores ---
    const int g = lane >> 2, tg = lane & 3;
    const int m_base = mT * BM + wm * 32;
    const int n_base = nT * BN + wn * 64;
#pragma unroll
    for (int mt = 0; mt < 2; mt++) {
#pragma unroll
        for (int nt = 0; nt < 8; nt++) {
            const int row = m_base + mt * 16 + g;
            const int col = n_base + nt * 8 + tg * 2;
            float2 v0 = make_float2((float)c[mt][nt][0], (float)c[mt][nt][1]);
            float2 v1 = make_float2((float)c[mt][nt][2], (float)c[mt][nt][3]);
            *reinterpret_cast<float2*>(out + (size_t)row * N_DIM + col) = v0;
            *reinterpret_cast<float2*>(out + (size_t)(row + 8) * N_DIM + col) = v1;
        }
    }
}

// ---------------------------------------------------------------------------
// Host
// ---------------------------------------------------------------------------
extern "C" void kernel_launch(void* const* d_in, const int* in_sizes, int n_in,
                              void* d_out, int out_size) {
    const float* x = (const float*)d_in[0];
    const float* w = (const float*)d_in[1];
    float* out = (float*)d_out;

    // 1) binarize x -> g_xa
    {
        int n16 = (M_DIM * K_DIM) / 16;
        binarize_x_kernel<<<n16 / 256, 256>>>((const float4*)x, n16);
    }
    // 2) binarize + transpose w -> g_wt [N,K]
    binarize_wT_kernel<<<dim3(N_DIM / 32, K_DIM / 32), dim3(32, 8)>>>(w);

    // 3) int8 tensor-core GEMM
    static bool attr_set = false;
    if (!attr_set) {
        cudaFuncSetAttribute(gemm_kernel, cudaFuncAttributeMaxDynamicSharedMemorySize,
                             SMEM_TOTAL);
        attr_set = true;
    }
    gemm_kernel<<<M_TILES * N_TILES, THREADS, SMEM_TOTAL>>>(out);
}